// round 10
// baseline (speedup 1.0000x reference)
#include <cuda_runtime.h>
#include <cuda_bf16.h>
#include <cstdint>

#define BB   128
#define SS   64
#define DD   32
#define ND   200000
#define NNZT 4000000
#define NW   6250   // ND/32
#define WPR  6256   // padded words/row

// ---------------- device scratch ----------------
__device__ float    g_s_set[BB * DD];
__device__ float    g_common[BB * DD];
__device__ float    g_colsum[ND];
__device__ float    g_dinv[ND];
__device__ float    g_diffacc[BB * DD];
__device__ float    g_cdacc[BB * DD];
__device__ float    g_sdiff[BB];
__device__ unsigned g_bits[BB * WPR];
__device__ double   g_bce;
__device__ double   g_neg1;

// ---------------- packed f32x2 helpers ----------------
__device__ __forceinline__ unsigned long long pk2(float lo, float hi) {
    unsigned long long r;
    asm("mov.b64 %0, {%1, %2};" : "=l"(r) : "f"(lo), "f"(hi));
    return r;
}
__device__ __forceinline__ void ffma2(unsigned long long& acc,
                                      unsigned long long a, unsigned long long b) {
    asm("fma.rn.f32x2 %0, %1, %2, %0;" : "+l"(acc) : "l"(a), "l"(b));
}
__device__ __forceinline__ float hsum2(unsigned long long a, unsigned long long b) {
    unsigned long long s;
    asm("add.rn.f32x2 %0, %1, %2;" : "=l"(s) : "l"(a), "l"(b));
    float x, y;
    asm("mov.b64 {%0, %1}, %2;" : "=f"(x), "=f"(y) : "l"(s));
    return x + y;
}
__device__ __forceinline__ float fast_tanh(float x) {
    float r;
    asm("tanh.approx.f32 %0, %1;" : "=f"(r) : "f"(x));
    return r;
}

// ---------------- kernel 0: zero accumulators ----------------
__global__ void k_init() {
    int i = blockIdx.x * blockDim.x + threadIdx.x;
    if (i < BB * DD) { g_diffacc[i] = 0.f; g_cdacc[i] = 0.f; }
    if (i < BB) g_sdiff[i] = 0.f;
    if (i == 0) { g_bce = 0.0; g_neg1 = 0.0; }
}

// ---------------- kernel 1: pack binary drugs to bits ----------------
__global__ void k_pack(const float* __restrict__ drugs) {
    int lane = threadIdx.x & 31;
    int gw = blockIdx.x * (blockDim.x >> 5) + (threadIdx.x >> 5);
    int wstride = gridDim.x * (blockDim.x >> 5);
    int total = BB * NW;
    for (; gw < total; gw += wstride) {
        int row = gw / NW, word = gw - row * NW;
        float v = drugs[(size_t)row * ND + word * 32 + lane];
        unsigned m = __ballot_sync(0xffffffffu, v != 0.f);
        if (lane == 0) g_bits[row * WPR + word] = m;
    }
}

// ---------------- kernel 1b: per-drug inverse norms ----------------
__global__ void k_norm(const float* __restrict__ drug_emb) {
    int n = blockIdx.x * blockDim.x + threadIdx.x;
    if (n < ND) {
        const float4* rp = (const float4*)(drug_emb + (size_t)(n + 1) * DD);
        float ss = 0.f;
#pragma unroll
        for (int q = 0; q < DD / 4; q++) {
            float4 v = rp[q];
            ss += v.x * v.x + v.y * v.y + v.z * v.z + v.w * v.w;
        }
        g_dinv[n] = 1.0f / fmaxf(sqrtf(ss), 1e-12f);
    }
}

// ---------------- kernel 2: s_set + common_embed ----------------
__global__ void k_attn(const int* __restrict__ syms, const int* __restrict__ simidx,
                       const float* __restrict__ sym_emb,
                       const float* __restrict__ w, const float* __restrict__ bvec) {
    int b = blockIdx.x;
    int s = threadIdx.x;
    __shared__ float sw[DD];
    __shared__ float sl[SS];
    __shared__ float sred[SS][DD];
    __shared__ float smax, ssum;
    if (s < DD) sw[s] = w[s];
    float b0 = bvec[0];
    __syncthreads();

    int sym = syms[b * SS + s];
    float x[DD];
    {
        const float4* rp = (const float4*)(sym_emb + (size_t)sym * DD);
#pragma unroll
        for (int q = 0; q < DD / 4; q++) {
            float4 v = rp[q];
            x[4 * q + 0] = v.x; x[4 * q + 1] = v.y; x[4 * q + 2] = v.z; x[4 * q + 3] = v.w;
        }
    }
    float lg = 0.f;
#pragma unroll
    for (int k = 0; k < DD; k++) lg += x[k] * sw[k];
    lg += b0;
    sl[s] = lg;
    __syncthreads();
    if (s == 0) { float m = sl[0]; for (int j = 1; j < SS; j++) m = fmaxf(m, sl[j]); smax = m; }
    __syncthreads();
    float e = expf(lg - smax);
    sl[s] = e;
    __syncthreads();
    if (s == 0) { float t = 0.f; for (int j = 0; j < SS; j++) t += sl[j]; ssum = t; }
    __syncthreads();
    float alpha = e / ssum;
#pragma unroll
    for (int k = 0; k < DD; k++) sred[s][k] = alpha * x[k];
    __syncthreads();
    if (s < DD) {
        float acc = 0.f;
        for (int j = 0; j < SS; j++) acc += sred[j][s];
        float sq = acc * acc;
#pragma unroll
        for (int off = 16; off; off >>= 1) sq += __shfl_xor_sync(0xffffffffu, sq, off);
        float nrm = fmaxf(sqrtf(sq), 1e-12f);
        g_s_set[b * DD + s] = acc / nrm;
    }
    __syncthreads();

    int sb = simidx[b];
    int sym2 = syms[sb * SS + s];
    float vals = (float)(sym * sym2);
    float y[DD];
    {
        const float4* rp = (const float4*)(sym_emb + (size_t)s * DD);
#pragma unroll
        for (int q = 0; q < DD / 4; q++) {
            float4 v = rp[q];
            y[4 * q + 0] = vals * v.x; y[4 * q + 1] = vals * v.y;
            y[4 * q + 2] = vals * v.z; y[4 * q + 3] = vals * v.w;
        }
    }
    lg = 0.f;
#pragma unroll
    for (int k = 0; k < DD; k++) lg += y[k] * sw[k];
    lg += b0;
    sl[s] = lg;
    __syncthreads();
    if (s == 0) { float m = sl[0]; for (int j = 1; j < SS; j++) m = fmaxf(m, sl[j]); smax = m; }
    __syncthreads();
    e = expf(lg - smax);
    sl[s] = e;
    __syncthreads();
    if (s == 0) { float t = 0.f; for (int j = 0; j < SS; j++) t += sl[j]; ssum = t; }
    __syncthreads();
    alpha = e / ssum;
#pragma unroll
    for (int k = 0; k < DD; k++) sred[s][k] = alpha * y[k];
    __syncthreads();
    if (s < DD) {
        float acc = 0.f;
        for (int j = 0; j < SS; j++) acc += sred[j][s];
        g_common[b * DD + s] = acc;
    }
}

// ---------------- kernel 3: sparse diff/cd accumulation over bit rows ------
// grid = BB*4 (b, word-quarter), 256 threads (8 warps). lane = embed dim.
__global__ void __launch_bounds__(256) k_diffcd(
    const int* __restrict__ simidx, const float* __restrict__ drug_emb) {
    int b = blockIdx.x >> 2;
    int quarter = blockIdx.x & 3;
    int warp = threadIdx.x >> 5, lane = threadIdx.x & 31;
    int sb = simidx[b];
    const unsigned* ow_row = g_bits + (size_t)b * WPR;
    const unsigned* sw_row = g_bits + (size_t)sb * WPR;

    float accd = 0.f, accc = 0.f;
    int cnt = 0;
    int w0 = quarter * 1563;
    int w1 = min(w0 + 1563, NW);
    for (int w = w0 + warp; w < w1; w += 8) {
        unsigned ow = ow_row[w], sw = sw_row[w];
        unsigned x = ow ^ sw;     // diff bits (exact: drugs binary)
        unsigned a = ow & sw;     // cd bits
        cnt += __popc(x);
        while (x) {
            int j = __ffs(x) - 1; x &= (x - 1);
            int n = w * 32 + j;
            accd += drug_emb[(size_t)(n + 1) * DD + lane] * g_dinv[n];
        }
        while (a) {
            int j = __ffs(a) - 1; a &= (a - 1);
            int n = w * 32 + j;
            accc += drug_emb[(size_t)(n + 1) * DD + lane] * g_dinv[n];
        }
    }
    __shared__ float sd[8][DD], sc[8][DD];
    __shared__ int scnt[8];
    sd[warp][lane] = accd;
    sc[warp][lane] = accc;
    if (lane == 0) scnt[warp] = cnt;
    __syncthreads();
    if (warp == 0) {
        float t1 = 0.f, t2 = 0.f;
        int c = 0;
        for (int wq = 0; wq < 8; wq++) { t1 += sd[wq][lane]; t2 += sc[wq][lane]; c += scnt[wq]; }
        atomicAdd(&g_diffacc[b * DD + lane], t1);
        atomicAdd(&g_cdacc[b * DD + lane], t2);
        if (lane == 0) atomicAdd(&g_sdiff[b], (float)c);
    }
}

// ---------------- kernel 4: lean mainloop (dots + sigmoid only) ------------
__global__ void __launch_bounds__(256, 3) k_main(
    const float* __restrict__ drug_emb, float* __restrict__ out) {
    __shared__ float s_i[BB * 64];   // interleaved {s pair, c pair} x16 per b
    __shared__ float s_red[256];

    int tid = threadIdx.x;
    int n = blockIdx.x * 256 + tid;
    bool valid = (n < ND);

    // build interleaved vector table: [b][pk] -> {s2k,s2k+1, c2k,c2k+1}
    for (int i = tid; i < BB * DD; i += 256) {
        int b = i >> 5, k = i & 31;
        int base = b * 64 + (k >> 1) * 4 + (k & 1);
        s_i[base]     = g_s_set[i];
        s_i[base + 2] = g_common[i];
    }

    // normalized d row in packed regs
    unsigned long long d2[DD / 2];
    {
        int gn = valid ? n : (ND - 1);
        float inv = valid ? g_dinv[n] : 0.f;
        const float4* rp = (const float4*)(drug_emb + (size_t)(gn + 1) * DD);
#pragma unroll
        for (int q = 0; q < DD / 4; q++) {
            float4 v = rp[q];
            d2[2 * q]     = pk2(v.x * inv, v.y * inv);
            d2[2 * q + 1] = pk2(v.z * inv, v.w * inv);
        }
    }
    __syncthreads();

    const ulonglong2* si4 = (const ulonglong2*)s_i;   // [BB*16]: {s_pair, c_pair}
    float colsum = 0.f, zs = 0.f, as = 0.f;
    float* o = out + (valid ? n : 0);

    for (int b = 0; b < BB; b++) {
        unsigned long long a0 = 0ull, a1 = 0ull, c0 = 0ull, c1 = 0ull;
#pragma unroll
        for (int k = 0; k < DD / 2; k += 2) {
            ulonglong2 v0 = si4[b * 16 + k];
            ulonglong2 v1 = si4[b * 16 + k + 1];
            ffma2(a0, d2[k],     v0.x);
            ffma2(c0, d2[k],     v0.y);
            ffma2(a1, d2[k + 1], v1.x);
            ffma2(c1, d2[k + 1], v1.y);
        }
        float t = hsum2(a0, a1);
        float z = hsum2(c0, c1);

        float th = fast_tanh(0.5f * t);
        float score = (t > 0.f) ? __fmaf_rn(0.5f, th, 0.5f) : 0.f;
        if (valid) *o = score;
        o += ND;
        colsum += score;

        zs += z;            // Sigma z
        as += fabsf(z);     // Sigma |z|   (softplus(z) ~= (z+|z|)/2 for |z|>>20)
    }

    if (valid) g_colsum[n] = colsum;

    // Sigma max(z,0) = 0.5*(zs + as)
    s_red[tid] = 0.5f * zs + 0.5f * as;
    __syncthreads();
    for (int st = 128; st; st >>= 1) {
        if (tid < st) s_red[tid] += s_red[tid + st];
        __syncthreads();
    }
    if (tid == 0) atomicAdd(&g_bce, (double)s_red[0]);
}

// ---------------- kernel 5: batch_neg gather ----------------
__global__ void k_tail2(const int* __restrict__ idx, const float* __restrict__ val) {
    __shared__ float sred[256];
    int tid = threadIdx.x;
    int i = blockIdx.x * blockDim.x + tid;
    int stride = gridDim.x * blockDim.x;
    float acc = 0.f;
    for (int j = i; j < NNZT; j += stride) acc += val[j] * g_colsum[idx[j]];
    sred[tid] = acc;
    __syncthreads();
    for (int st = 128; st; st >>= 1) {
        if (tid < st) sred[tid] += sred[tid + st];
        __syncthreads();
    }
    if (tid == 0) atomicAdd(&g_neg1, (double)sred[0]);
}

// ---------------- kernel 6: scalars ----------------
__global__ void k_final(float* __restrict__ out) {
    int b = threadIdx.x;   // 128
    __shared__ float sred[BB];
    __shared__ double scd[BB];
    float acc = 0.f;
    double cdot = 0.0;
    float sdv = g_sdiff[b] + 1e-6f;
#pragma unroll
    for (int k = 0; k < DD; k++) {
        float cm = g_common[b * DD + k];
        cdot += (double)cm * (double)g_cdacc[b * DD + k];   // Sigma z*cd term
        float de = g_diffacc[b * DD + k] / sdv;
        float x = cm * de;
        acc += 1.0f / (1.0f + __expf(-x));
    }
    sred[b] = acc;
    scd[b] = cdot;
    __syncthreads();
    for (int st = 64; st; st >>= 1) {
        if (b < st) { sred[b] += sred[b + st]; scd[b] += scd[b + st]; }
        __syncthreads();
    }
    if (b == 0) {
        double total = g_bce - scd[0];
        out[(size_t)BB * ND]     = (float)(total / ((double)BB * (double)ND));
        out[(size_t)BB * ND + 1] = (float)(1e-6 * g_neg1 + 1e-4 * (double)sred[0]);
    }
}

// ---------------- launcher ----------------
extern "C" void kernel_launch(void* const* d_in, const int* in_sizes, int n_in,
                              void* d_out, int out_size) {
    const int*   syms     = (const int*)d_in[0];
    const float* drugs    = (const float*)d_in[1];
    const int*   simidx   = (const int*)d_in[2];
    const int*   ddi_idx  = (const int*)d_in[3];
    const float* ddi_val  = (const float*)d_in[4];
    const float* sym_emb  = (const float*)d_in[5];
    const float* drug_emb = (const float*)d_in[6];
    const float* attn_w   = (const float*)d_in[7];
    const float* attn_b   = (const float*)d_in[8];
    float* out = (float*)d_out;

    k_init<<<32, 256>>>();
    k_pack<<<1024, 256>>>(drugs);
    k_norm<<<(ND + 255) / 256, 256>>>(drug_emb);
    k_attn<<<BB, SS>>>(syms, simidx, sym_emb, attn_w, attn_b);
    k_diffcd<<<BB * 4, 256>>>(simidx, drug_emb);
    k_main<<<(ND + 255) / 256, 256>>>(drug_emb, out);
    k_tail2<<<1024, 256>>>(ddi_idx, ddi_val);
    k_final<<<1, BB>>>(out);
}